// round 3
// baseline (speedup 1.0000x reference)
#include <cuda_runtime.h>

#define BB 4
#define CC 64
#define FD 50000
#define KN 16
#define BN_EPS 1e-5f

// Scratch: transformed features g[b][f][o]  (face-major for coalesced gather)
__device__ float g_buf[BB * FD * CC];
__device__ float g_sum[CC];
__device__ float g_sq[CC];
__device__ float g_scale[CC];
__device__ float g_shift[CC];

// ---------------------------------------------------------------------------
__global__ void zero_stats_kernel() {
    int t = threadIdx.x;
    if (t < CC) { g_sum[t] = 0.f; g_sq[t] = 0.f; }
}

// ---------------------------------------------------------------------------
// GEMM: g[b][f][o] = sum_c W[o][c] * fea[b][c][f]
// Block: 256 threads, tile 128 faces x 64 outputs, 4x8 register microtile.
__global__ __launch_bounds__(256) void gemm_kernel(const float* __restrict__ fea,
                                                   const float* __restrict__ W) {
    __shared__ float sF[64][128];   // [c][f]  32 KB
    __shared__ float sW[64][64];    // [o][c]  16 KB
    const int b = blockIdx.y;
    const int f0 = blockIdx.x * 128;
    const int t = threadIdx.x;

    const float* feab = fea + (size_t)b * (CC * FD);
    for (int i = t; i < 64 * 128; i += 256) {
        int c = i >> 7, f = i & 127;
        int fg = f0 + f;
        sF[c][f] = (fg < FD) ? feab[c * FD + fg] : 0.f;
    }
    for (int i = t; i < 64 * 64; i += 256) {
        sW[i >> 6][i & 63] = W[i];
    }
    __syncthreads();

    const int tx = t & 31;   // face lane
    const int ty = t >> 5;   // output group 0..7
    float acc[4][8];
#pragma unroll
    for (int i = 0; i < 4; i++)
#pragma unroll
        for (int j = 0; j < 8; j++) acc[i][j] = 0.f;

#pragma unroll 4
    for (int c = 0; c < 64; c++) {
        float a0 = sF[c][tx];
        float a1 = sF[c][tx + 32];
        float a2 = sF[c][tx + 64];
        float a3 = sF[c][tx + 96];
#pragma unroll
        for (int j = 0; j < 8; j++) {
            float w = sW[ty * 8 + j][c];   // warp-uniform broadcast
            acc[0][j] += a0 * w;
            acc[1][j] += a1 * w;
            acc[2][j] += a2 * w;
            acc[3][j] += a3 * w;
        }
    }

    float* gb = g_buf + (size_t)b * (FD * CC);
#pragma unroll
    for (int i = 0; i < 4; i++) {
        int fg = f0 + tx + 32 * i;
        if (fg < FD) {
            float4 v0 = make_float4(acc[i][0], acc[i][1], acc[i][2], acc[i][3]);
            float4 v1 = make_float4(acc[i][4], acc[i][5], acc[i][6], acc[i][7]);
            float4* p = (float4*)(gb + (size_t)fg * CC + ty * 8);
            p[0] = v0;
            p[1] = v1;
        }
    }
}

// ---------------------------------------------------------------------------
// Gather + bias + stats, writes y into d_out in [B, C, F] layout.
// Block: 256 threads = 8 warps; warp w handles faces f0+4w .. f0+4w+3.
// Lane owns channels (2*lane, 2*lane+1) -> one LDG.64 per neighbor row.
// ring is int32 (JAX default x64-disabled demotes jnp.int64 -> int32).
__global__ __launch_bounds__(256) void gather_kernel(const int* __restrict__ ring,
                                                     const float* __restrict__ bias,
                                                     float* __restrict__ out) {
    __shared__ float tile[32][65];      // [f_local][c], padded for conflict-free read
    __shared__ float s_sum[CC];
    __shared__ float s_sq[CC];

    const int t = threadIdx.x;
    if (t < CC) { s_sum[t] = 0.f; s_sq[t] = 0.f; }
    __syncthreads();

    const int b = blockIdx.y;
    const int f0 = blockIdx.x * 32;
    const int warp = t >> 5, lane = t & 31;
    const float* gb = g_buf + (size_t)b * (FD * CC);
    const float bias0 = bias[2 * lane];
    const float bias1 = bias[2 * lane + 1];

    float s0 = 0.f, s1 = 0.f, q0 = 0.f, q1 = 0.f;

#pragma unroll
    for (int i = 0; i < 4; i++) {
        int f = f0 + warp * 4 + i;              // warp-uniform
        if (f >= FD) continue;
        const int* rp = ring + ((long long)(b * FD + f)) * KN;
        int myidx = (lane < KN) ? rp[lane] : 0;
        // defensive bounds guard: OOB index -> 0 (wrong-answer signal, not crash)
        if ((unsigned)myidx >= (unsigned)FD) myidx = 0;
        float accx = 0.f, accy = 0.f;
#pragma unroll
        for (int k = 0; k < KN; k++) {
            int idx = __shfl_sync(0xffffffffu, myidx, k);
            float2 v = *(const float2*)(gb + (size_t)idx * CC + 2 * lane);
            accx += v.x;
            accy += v.y;
        }
        float y0 = accx + bias0;
        float y1 = accy + bias1;
        tile[warp * 4 + i][2 * lane]     = y0;
        tile[warp * 4 + i][2 * lane + 1] = y1;
        s0 += y0; q0 += y0 * y0;
        s1 += y1; q1 += y1 * y1;
    }

    atomicAdd(&s_sum[2 * lane],     s0);
    atomicAdd(&s_sum[2 * lane + 1], s1);
    atomicAdd(&s_sq[2 * lane],      q0);
    atomicAdd(&s_sq[2 * lane + 1],  q1);
    __syncthreads();

    // Transposed, coalesced write: out[b][c][f0+lane]
    const int nf = min(32, FD - f0);
    for (int c = warp; c < CC; c += 8) {
        if (lane < nf)
            out[((size_t)b * CC + c) * FD + f0 + lane] = tile[lane][c];
    }

    if (t < CC) {
        atomicAdd(&g_sum[t], s_sum[t]);
        atomicAdd(&g_sq[t],  s_sq[t]);
    }
}

// ---------------------------------------------------------------------------
__global__ void finalize_kernel(const float* __restrict__ gamma,
                                const float* __restrict__ beta) {
    int c = threadIdx.x;
    if (c < CC) {
        const float inv_n = 1.0f / (float)(BB * FD);
        float mean = g_sum[c] * inv_n;
        float var  = g_sq[c] * inv_n - mean * mean;
        float sc = gamma[c] * rsqrtf(var + BN_EPS);
        g_scale[c] = sc;
        g_shift[c] = beta[c] - mean * sc;
    }
}

// ---------------------------------------------------------------------------
// In-place normalize + ReLU over d_out, float4 vectorized.
// Total float4 = 4*64*50000/4 = 3,200,000 = 12500 blocks * 256 threads exactly.
__global__ __launch_bounds__(256) void norm_kernel(float* __restrict__ out) {
    int i = blockIdx.x * 256 + threadIdx.x;       // float4 index
    int c = (i / (FD / 4)) & 63;                  // channel
    float4 v = ((float4*)out)[i];
    float sc = g_scale[c], sh = g_shift[c];
    v.x = fmaxf(fmaf(v.x, sc, sh), 0.f);
    v.y = fmaxf(fmaf(v.y, sc, sh), 0.f);
    v.z = fmaxf(fmaf(v.z, sc, sh), 0.f);
    v.w = fmaxf(fmaf(v.w, sc, sh), 0.f);
    ((float4*)out)[i] = v;
}

// ---------------------------------------------------------------------------
extern "C" void kernel_launch(void* const* d_in, const int* in_sizes, int n_in,
                              void* d_out, int out_size) {
    const float* fea   = (const float*)d_in[0];      // [B, C_in, F]
    const int*   ring  = (const int*)d_in[1];        // [B, F, K] int32
    const float* W     = (const float*)d_in[2];      // [C_out, C_in]
    const float* bias  = (const float*)d_in[3];      // [C_out]
    const float* gamma = (const float*)d_in[4];      // [C_out]
    const float* beta  = (const float*)d_in[5];      // [C_out]
    float*       out   = (float*)d_out;              // [B, C_out, F]

    zero_stats_kernel<<<1, 128>>>();

    dim3 gg((FD + 127) / 128, BB);
    gemm_kernel<<<gg, 256>>>(fea, W);

    dim3 gt((FD + 31) / 32, BB);
    gather_kernel<<<gt, 256>>>(ring, bias, out);

    finalize_kernel<<<1, 64>>>(gamma, beta);

    norm_kernel<<<(BB * CC * FD / 4) / 256, 256>>>(out);
}

// round 4
// speedup vs baseline: 1.1360x; 1.1360x over previous
#include <cuda_runtime.h>
#include <cuda_fp16.h>

#define BB 4
#define CC 64
#define FD 50000
#define KN 16
#define BN_EPS 1e-5f

// Scratch: transformed features g[b][f][o] in fp16 (face-major, 128B rows)
__device__ __half g_buf[BB * FD * CC];
__device__ float g_sum[CC];
__device__ float g_sq[CC];

// ---------------------------------------------------------------------------
// Packed f32x2 helpers (Blackwell FFMA2 path — ptxas won't auto-fuse this)
__device__ __forceinline__ unsigned long long pk2(float x, float y) {
    unsigned long long r;
    asm("mov.b64 %0, {%1, %2};" : "=l"(r) : "f"(x), "f"(y));
    return r;
}
__device__ __forceinline__ void upk2(unsigned long long v, float& x, float& y) {
    asm("mov.b64 {%0, %1}, %2;" : "=f"(x), "=f"(y) : "l"(v));
}
__device__ __forceinline__ void fma2(unsigned long long& d,
                                     unsigned long long a,
                                     unsigned long long b) {
    asm("fma.rn.f32x2 %0, %1, %2, %0;" : "+l"(d) : "l"(a), "l"(b));
}

// ---------------------------------------------------------------------------
// GEMM: g[b][f][o] = sum_c W[o][c] * fea[b][c][f], fp16 output.
// Block: 256 threads, tile 128 faces x 64 outputs.
// Microtile: 4 faces x 8 outputs per thread, outputs packed in f32x2 pairs.
__global__ __launch_bounds__(256) void gemm_kernel(const float* __restrict__ fea,
                                                   const float* __restrict__ W) {
    __shared__ float  sF[64][128];    // [c][f]    32 KB
    __shared__ float2 sW2[64][32];    // [c][o/2]  16 KB, pair loads as LDS.64
    const int b = blockIdx.y;
    const int f0 = blockIdx.x * 128;
    const int t = threadIdx.x;

    // fold stats zeroing into this kernel (runs before gather)
    if (f0 == 0 && b == 0 && t < CC) { g_sum[t] = 0.f; g_sq[t] = 0.f; }

    const float* feab = fea + (size_t)b * (CC * FD);
    for (int i = t; i < 64 * 128; i += 256) {
        int c = i >> 7, f = i & 127;
        int fg = f0 + f;
        sF[c][f] = (fg < FD) ? feab[c * FD + fg] : 0.f;
    }
    // sW2[c][jj] = (W[2jj][c], W[2jj+1][c]); W is tiny, L2-cached
    for (int i = t; i < 64 * 32; i += 256) {
        int c = i >> 5, jj = i & 31;
        sW2[c][jj] = make_float2(W[(2 * jj) * CC + c], W[(2 * jj + 1) * CC + c]);
    }
    __syncthreads();

    const int tx = t & 31;   // face lane
    const int ty = t >> 5;   // output group 0..7 (outputs ty*8 .. ty*8+7)
    unsigned long long acc2[4][4];
#pragma unroll
    for (int i = 0; i < 4; i++)
#pragma unroll
        for (int j = 0; j < 4; j++) acc2[i][j] = 0ull;

#pragma unroll 4
    for (int c = 0; c < 64; c++) {
        unsigned long long pa0 = pk2(sF[c][tx],      sF[c][tx]);
        unsigned long long pa1 = pk2(sF[c][tx + 32], sF[c][tx + 32]);
        unsigned long long pa2 = pk2(sF[c][tx + 64], sF[c][tx + 64]);
        unsigned long long pa3 = pk2(sF[c][tx + 96], sF[c][tx + 96]);
#pragma unroll
        for (int jj = 0; jj < 4; jj++) {
            unsigned long long w2 =
                *(const unsigned long long*)&sW2[c][ty * 4 + jj];  // broadcast LDS.64
            fma2(acc2[0][jj], pa0, w2);
            fma2(acc2[1][jj], pa1, w2);
            fma2(acc2[2][jj], pa2, w2);
            fma2(acc2[3][jj], pa3, w2);
        }
    }

    __half* gb = g_buf + (size_t)b * (FD * CC);
#pragma unroll
    for (int i = 0; i < 4; i++) {
        int fg = f0 + tx + 32 * i;
        if (fg < FD) {
            union { __half2 h[4]; uint4 u; } pk;
#pragma unroll
            for (int jj = 0; jj < 4; jj++) {
                float lo, hi;
                upk2(acc2[i][jj], lo, hi);
                pk.h[jj] = __floats2half2_rn(lo, hi);
            }
            *(uint4*)(gb + (size_t)fg * CC + ty * 8) = pk.u;  // 16B store
        }
    }
}

// ---------------------------------------------------------------------------
// Gather + bias + stats, writes y into d_out in [B, C, F] layout.
// Warp per 4 faces; lane owns channels (2*lane, 2*lane+1) -> one LDG.32
// (half2) per neighbor row. fp32 accumulation.
__global__ __launch_bounds__(256) void gather_kernel(const int* __restrict__ ring,
                                                     const float* __restrict__ bias,
                                                     float* __restrict__ out) {
    __shared__ float tile[32][65];      // [f_local][c], padded
    __shared__ float s_sum[CC];
    __shared__ float s_sq[CC];

    const int t = threadIdx.x;
    if (t < CC) { s_sum[t] = 0.f; s_sq[t] = 0.f; }
    __syncthreads();

    const int b = blockIdx.y;
    const int f0 = blockIdx.x * 32;
    const int warp = t >> 5, lane = t & 31;
    const __half2* gb = (const __half2*)(g_buf + (size_t)b * (FD * CC));
    const float bias0 = bias[2 * lane];
    const float bias1 = bias[2 * lane + 1];

    float s0 = 0.f, s1 = 0.f, q0 = 0.f, q1 = 0.f;

#pragma unroll
    for (int i = 0; i < 4; i++) {
        int f = f0 + warp * 4 + i;              // warp-uniform
        if (f >= FD) continue;
        const int* rp = ring + ((long long)(b * FD + f)) * KN;
        int myidx = (lane < KN) ? rp[lane] : 0;
        if ((unsigned)myidx >= (unsigned)FD) myidx = 0;   // defensive
        float accx = 0.f, accy = 0.f;
#pragma unroll
        for (int k = 0; k < KN; k++) {
            int idx = __shfl_sync(0xffffffffu, myidx, k);
            float2 v = __half22float2(gb[(size_t)idx * 32 + lane]);
            accx += v.x;
            accy += v.y;
        }
        float y0 = accx + bias0;
        float y1 = accy + bias1;
        tile[warp * 4 + i][2 * lane]     = y0;
        tile[warp * 4 + i][2 * lane + 1] = y1;
        s0 += y0; q0 += y0 * y0;
        s1 += y1; q1 += y1 * y1;
    }

    atomicAdd(&s_sum[2 * lane],     s0);
    atomicAdd(&s_sum[2 * lane + 1], s1);
    atomicAdd(&s_sq[2 * lane],      q0);
    atomicAdd(&s_sq[2 * lane + 1],  q1);
    __syncthreads();

    // Transposed, coalesced write: out[b][c][f0+lane]
    const int nf = min(32, FD - f0);
    for (int c = warp; c < CC; c += 8) {
        if (lane < nf)
            out[((size_t)b * CC + c) * FD + f0 + lane] = tile[lane][c];
    }

    if (t < CC) {
        atomicAdd(&g_sum[t], s_sum[t]);
        atomicAdd(&g_sq[t],  s_sq[t]);
    }
}

// ---------------------------------------------------------------------------
// In-place normalize + ReLU over d_out, float4 vectorized, BN finalize inline.
// 3,200,000 float4 = 12500 blocks x 256 threads exactly.
__global__ __launch_bounds__(256) void norm_kernel(const float* __restrict__ gamma,
                                                   const float* __restrict__ beta,
                                                   float* __restrict__ out) {
    int i = blockIdx.x * 256 + threadIdx.x;       // float4 index
    int c = (i / (FD / 4)) & 63;                  // channel
    const float inv_n = 1.0f / (float)(BB * FD);
    float mean = g_sum[c] * inv_n;
    float var  = g_sq[c] * inv_n - mean * mean;
    float sc = gamma[c] * rsqrtf(var + BN_EPS);
    float sh = beta[c] - mean * sc;
    float4 v = ((float4*)out)[i];
    v.x = fmaxf(fmaf(v.x, sc, sh), 0.f);
    v.y = fmaxf(fmaf(v.y, sc, sh), 0.f);
    v.z = fmaxf(fmaf(v.z, sc, sh), 0.f);
    v.w = fmaxf(fmaf(v.w, sc, sh), 0.f);
    ((float4*)out)[i] = v;
}

// ---------------------------------------------------------------------------
extern "C" void kernel_launch(void* const* d_in, const int* in_sizes, int n_in,
                              void* d_out, int out_size) {
    const float* fea   = (const float*)d_in[0];      // [B, C_in, F]
    const int*   ring  = (const int*)d_in[1];        // [B, F, K] int32
    const float* W     = (const float*)d_in[2];      // [C_out, C_in]
    const float* bias  = (const float*)d_in[3];      // [C_out]
    const float* gamma = (const float*)d_in[4];      // [C_out]
    const float* beta  = (const float*)d_in[5];      // [C_out]
    float*       out   = (float*)d_out;              // [B, C_out, F]

    dim3 gg((FD + 127) / 128, BB);
    gemm_kernel<<<gg, 256>>>(fea, W);

    dim3 gt((FD + 31) / 32, BB);
    gather_kernel<<<gt, 256>>>(ring, bias, out);

    norm_kernel<<<(BB * CC * FD / 4) / 256, 256>>>(gamma, beta, out);
}